// round 15
// baseline (speedup 1.0000x reference)
#include <cuda_runtime.h>
#include <cuda_fp16.h>
#include <cstdint>
#include <math.h>

#define N_TOK 4096
#define DDIM  512
#define KEEP  2048

// ---------------- device scratch (uint4 for 16B alignment) ----------------
__device__ uint4 g_xh  [N_TOK * DDIM / 8];
__device__ uint4 g_WTh [3 * DDIM * DDIM / 8];
__device__ uint4 g_qh  [N_TOK * DDIM / 8];
__device__ uint4 g_kh  [N_TOK * DDIM / 8];
__device__ uint4 g_vh  [N_TOK * DDIM / 8];
__device__ uint4 g_kTh [N_TOK * DDIM / 8];
__device__ uint4 g_vTh [N_TOK * DDIM / 8];
__device__ uint4 g_scoreh[(size_t)N_TOK * N_TOK / 8];
__device__ uint4 g_atth  [(size_t)N_TOK * N_TOK / 8];

typedef __half fp16;

// ---------------- helpers ----------------
__device__ __forceinline__ uint32_t smem_u32(const void* p) {
    uint32_t a;
    asm("{ .reg .u64 t; cvta.to.shared.u64 t, %1; cvt.u32.u64 %0, t; }"
        : "=r"(a) : "l"(p));
    return a;
}

#define CP16(dst, src) \
    asm volatile("cp.async.cg.shared.global [%0], [%1], 16;" :: "r"(dst), "l"(src) : "memory")
#define CP_COMMIT() asm volatile("cp.async.commit_group;" ::: "memory")
#define CP_WAIT1()  asm volatile("cp.async.wait_group 1;" ::: "memory")
#define CP_WAIT0()  asm volatile("cp.async.wait_group 0;" ::: "memory")

#define LDSM4(r, a)                                                             \
    asm volatile("ldmatrix.sync.aligned.m8n8.x4.shared.b16 {%0,%1,%2,%3}, [%4];" \
        : "=r"((r)[0]), "=r"((r)[1]), "=r"((r)[2]), "=r"((r)[3]) : "r"(a))

// m16n8k16 fp16 MMA, D += A*B (row.col), f32 accumulate
#define MMA16(cc, a, b)                                                         \
    asm volatile("mma.sync.aligned.m16n8k16.row.col.f32.f16.f16.f32 "           \
        "{%0,%1,%2,%3}, {%4,%5,%6,%7}, {%8,%9}, {%0,%1,%2,%3};"                 \
        : "+f"((cc)[0]), "+f"((cc)[1]), "+f"((cc)[2]), "+f"((cc)[3])            \
        : "r"((a)[0]), "r"((a)[1]), "r"((a)[2]), "r"((a)[3]),                   \
          "r"((b)[0]), "r"((b)[1]))

// ---------------------------------------------------------------------------
// Plain fp16 GEMM body 128x128 (f32 accum): C = scale*(A @ B^T) (+bias)
// BK=64, 512 threads, 16 warps 4x4, warp tile 32x32.
// Smem: 2 stages x 2 tiles x 128 rows x 144B = 73728 B -> 2 CTAs/SM.
// ---------------------------------------------------------------------------
#define TILE_B    18432
#define STAGE_ALL (2 * TILE_B)
#define GEMM_SMEM_BYTES (2 * STAGE_ALL)    // 73728

template<bool BIAS, bool HALF_OUT>
__device__ __forceinline__ void gemm_body(
    const fp16* __restrict__ A, int lda,
    const fp16* __restrict__ B, int ldb,
    float* __restrict__ C, fp16* __restrict__ Ch, int ldc,
    int K, const float* __restrict__ bias, float scale,
    int bx, int by, char* sm)
{
    const uint32_t smb = smem_u32(sm);

    const int tid  = threadIdx.x;
    const int w    = tid >> 5;
    const int lane = tid & 31;
    const int wm   = w & 3;
    const int wn   = w >> 2;
    const int g    = lane >> 2;
    const int tig  = lane & 3;

    const int lrow = tid >> 2;
    const int lch  = tid & 3;
    const fp16* pA = A + (size_t)(by * 128 + lrow) * lda + lch * 16;
    const fp16* pB = B + (size_t)(bx * 128 + lrow) * ldb + lch * 16;
    const uint32_t so = (uint32_t)lrow * 144 + lch * 32;

    const int l7 = lane & 7;
    const uint32_t aoff0 = (uint32_t)(wm * 32 + ((lane >> 3) & 1) * 8 + l7) * 144
                         + (uint32_t)(lane >> 4) * 16;
    const uint32_t aoff1 = aoff0 + 16u * 144u;
    const uint32_t boff0 = TILE_B
                         + (uint32_t)(wn * 32 + (lane >> 4) * 8 + l7) * 144
                         + (uint32_t)((lane >> 3) & 1) * 16;
    const uint32_t boff1 = boff0 + 16u * 144u;

    float c[2][4][4] = {};
    const int nT = K >> 6;

    {
        const uint32_t st = smb;
        CP16(st + so,               pA);
        CP16(st + so + 16,          pA + 8);
        CP16(st + TILE_B + so,      pB);
        CP16(st + TILE_B + so + 16, pB + 8);
        CP_COMMIT();
    }

    for (int kt = 0; kt < nT; ++kt) {
        if (kt + 1 < nT) {
            const uint32_t st = smb + ((kt + 1) & 1) * STAGE_ALL;
            const int ko = (kt + 1) * 64;
            CP16(st + so,               pA + ko);
            CP16(st + so + 16,          pA + ko + 8);
            CP16(st + TILE_B + so,      pB + ko);
            CP16(st + TILE_B + so + 16, pB + ko + 8);
            CP_COMMIT();
            CP_WAIT1();
        } else {
            CP_WAIT0();
        }
        __syncthreads();

        const uint32_t stb = smb + (kt & 1) * STAGE_ALL;

        #pragma unroll
        for (int ks = 0; ks < 4; ++ks) {
            const uint32_t koff = (uint32_t)ks * 32;

            uint32_t ah[2][4], bh[2][4];
            LDSM4(ah[0], stb + aoff0 + koff);
            LDSM4(ah[1], stb + aoff1 + koff);
            LDSM4(bh[0], stb + boff0 + koff);
            LDSM4(bh[1], stb + boff1 + koff);

            #pragma unroll
            for (int mi = 0; mi < 2; ++mi)
                #pragma unroll
                for (int ni = 0; ni < 4; ++ni)
                    MMA16(c[mi][ni], ah[mi], bh[ni >> 1] + (ni & 1) * 2);
        }
        __syncthreads();
    }

    #pragma unroll
    for (int mi = 0; mi < 2; ++mi) {
        const int r0 = by * 128 + wm * 32 + mi * 16 + g;
        #pragma unroll
        for (int ni = 0; ni < 4; ++ni) {
            const int col = bx * 128 + wn * 32 + ni * 8 + tig * 2;
            float vv[4];
            vv[0] = c[mi][ni][0] * scale; vv[1] = c[mi][ni][1] * scale;
            vv[2] = c[mi][ni][2] * scale; vv[3] = c[mi][ni][3] * scale;
            if (BIAS) {
                const float b0 = bias[col], b1 = bias[col + 1];
                vv[0] += b0; vv[1] += b1; vv[2] += b0; vv[3] += b1;
            }
            if (HALF_OUT) {
                __half2 t2;
                t2.x = __float2half_rn(vv[0]); t2.y = __float2half_rn(vv[1]);
                *reinterpret_cast<__half2*>(Ch + (size_t)r0 * ldc + col) = t2;
                t2.x = __float2half_rn(vv[2]); t2.y = __float2half_rn(vv[3]);
                *reinterpret_cast<__half2*>(Ch + (size_t)(r0 + 8) * ldc + col) = t2;
            } else {
                *reinterpret_cast<float2*>(C + (size_t)r0 * ldc + col)       = make_float2(vv[0], vv[1]);
                *reinterpret_cast<float2*>(C + (size_t)(r0 + 8) * ldc + col) = make_float2(vv[2], vv[3]);
            }
        }
    }
}

template<bool BIAS, bool HALF_OUT>
__global__ void __launch_bounds__(512, 2)
mma_hf_kernel(const fp16* __restrict__ A, int lda,
              const fp16* __restrict__ B, int ldb,
              float* __restrict__ C, fp16* __restrict__ Ch,
              int ldc, int K, const float* __restrict__ bias, float scale)
{
    extern __shared__ char sm[];
    gemm_body<BIAS, HALF_OUT>(A, lda, B, ldb, C, Ch, ldc,
                              K, bias, scale, blockIdx.x, blockIdx.y, sm);
}

// Merged QKV: grid (4, 32, 3); all outputs fp16.
__global__ void __launch_bounds__(512, 2)
qkv_kernel(const fp16* __restrict__ xh, const fp16* __restrict__ WTh,
           const float* __restrict__ bq, const float* __restrict__ bk,
           const float* __restrict__ bv,
           fp16* __restrict__ qh, fp16* __restrict__ kh, fp16* __restrict__ vh)
{
    extern __shared__ char sm[];
    const int z = blockIdx.z;
    const fp16* Wh = WTh + (size_t)z * DDIM * DDIM;
    fp16* outp = (z == 0) ? qh : (z == 1) ? kh : vh;
    const float* bias = (z == 0) ? bq : (z == 1) ? bk : bv;
    gemm_body<true, true>(xh, DDIM, Wh, DDIM, nullptr, outp,
                          DDIM, DDIM, bias, 1.0f, blockIdx.x, blockIdx.y, sm);
}

// ---------------------------------------------------------------------------
// ctx GEMM, tile 128x64, NO split-K: out[M=4096, N=512] f32 = attn @ vT^T.
// K=4096 unsplit. Grid (8, 32) = 256 CTAs -> same 86.5% wave util as
// split-2 but no partials, no reduce. Warp tile 32x16 (4x4 warps, ni<2).
// Smem: 2 stages x (A 128 + B 64 rows) x 144B = 55296 B -> 2 CTAs/SM.
// ---------------------------------------------------------------------------
#define CTILE_A   18432                    // 128 * 144
#define CTILE_B   9216                     // 64 * 144
#define CSTAGE    (CTILE_A + CTILE_B)      // 27648
#define CTX_SMEM_BYTES (2 * CSTAGE)        // 55296

__global__ void __launch_bounds__(512, 2)
ctx_kernel(const fp16* __restrict__ atth, const fp16* __restrict__ vTh,
           float* __restrict__ outp)
{
    extern __shared__ char sm[];
    const uint32_t smb = smem_u32(sm);
    const int bx = blockIdx.x, by = blockIdx.y;

    const int tid  = threadIdx.x;
    const int w    = tid >> 5;
    const int lane = tid & 31;
    const int wm   = w & 3;
    const int wn   = w >> 2;
    const int g    = lane >> 2;
    const int tig  = lane & 3;

    // A loader: 128 rows x 128B; thread t -> row t>>2, 32B chunk t&3 (2 CP16)
    const int arow = tid >> 2;
    const int ach  = tid & 3;
    const fp16* pA = atth + (size_t)(by * 128 + arow) * N_TOK + ach * 16;
    const uint32_t soA = (uint32_t)arow * 144 + ach * 32;
    // B loader: 64 rows x 128B = 512 x 16B chunks; thread t -> row t>>3, chunk t&7 (1 CP16)
    const int brow = tid >> 3;
    const int bch  = tid & 7;
    const fp16* pB = vTh + (size_t)(bx * 64 + brow) * N_TOK + bch * 8;
    const uint32_t soB = CTILE_A + (uint32_t)brow * 144 + bch * 16;

    const int l7 = lane & 7;
    const uint32_t aoff0 = (uint32_t)(wm * 32 + ((lane >> 3) & 1) * 8 + l7) * 144
                         + (uint32_t)(lane >> 4) * 16;
    const uint32_t aoff1 = aoff0 + 16u * 144u;
    const uint32_t boff  = CTILE_A
                         + (uint32_t)(wn * 16 + (lane >> 4) * 8 + l7) * 144
                         + (uint32_t)((lane >> 3) & 1) * 16;

    float c[2][2][4] = {};
    const int nT = N_TOK >> 6;   // 64 k-tiles

    {
        const uint32_t st = smb;
        CP16(st + soA,      pA);
        CP16(st + soA + 16, pA + 8);
        CP16(st + soB,      pB);
        CP_COMMIT();
    }

    for (int kt = 0; kt < nT; ++kt) {
        if (kt + 1 < nT) {
            const uint32_t st = smb + ((kt + 1) & 1) * CSTAGE;
            const int ko = (kt + 1) * 64;
            CP16(st + soA,      pA + ko);
            CP16(st + soA + 16, pA + ko + 8);
            CP16(st + soB,      pB + ko);
            CP_COMMIT();
            CP_WAIT1();
        } else {
            CP_WAIT0();
        }
        __syncthreads();

        const uint32_t stb = smb + (kt & 1) * CSTAGE;

        #pragma unroll
        for (int ks = 0; ks < 4; ++ks) {
            const uint32_t koff = (uint32_t)ks * 32;

            uint32_t ah[2][4], bh[4];
            LDSM4(ah[0], stb + aoff0 + koff);
            LDSM4(ah[1], stb + aoff1 + koff);
            LDSM4(bh,    stb + boff  + koff);

            #pragma unroll
            for (int mi = 0; mi < 2; ++mi)
                #pragma unroll
                for (int ni = 0; ni < 2; ++ni)
                    MMA16(c[mi][ni], ah[mi], bh + ni * 2);
        }
        __syncthreads();
    }

    #pragma unroll
    for (int mi = 0; mi < 2; ++mi) {
        const int r0 = by * 128 + wm * 32 + mi * 16 + g;
        #pragma unroll
        for (int ni = 0; ni < 2; ++ni) {
            const int col = bx * 64 + wn * 16 + ni * 8 + tig * 2;
            *reinterpret_cast<float2*>(outp + (size_t)r0 * DDIM + col) =
                make_float2(c[mi][ni][0], c[mi][ni][1]);
            *reinterpret_cast<float2*>(outp + (size_t)(r0 + 8) * DDIM + col) =
                make_float2(c[mi][ni][2], c[mi][ni][3]);
        }
    }
}

// ---------------------------------------------------------------------------
// Elementwise f32 -> fp16 convert
// ---------------------------------------------------------------------------
__global__ void __launch_bounds__(256)
cvt_kernel(const float* __restrict__ in, fp16* __restrict__ outp)
{
    const int i = blockIdx.x * blockDim.x + threadIdx.x;
    outp[i] = __float2half_rn(in[i]);
}

// ---------------------------------------------------------------------------
// 32x32 tiled transpose, f32 in -> fp16 out (weights). Merged via grid.z.
// ---------------------------------------------------------------------------
__device__ __forceinline__ void transpose_hi_body(
    const float* __restrict__ in, fp16* __restrict__ hi, int R, int C)
{
    __shared__ float t[32][33];
    const int bx = blockIdx.x * 32, by = blockIdx.y * 32;
    const int tx = threadIdx.x, ty = threadIdx.y;
    #pragma unroll
    for (int j = 0; j < 32; j += 8)
        t[ty + j][tx] = in[(size_t)(by + ty + j) * C + bx + tx];
    __syncthreads();
    #pragma unroll
    for (int j = 0; j < 32; j += 8)
        hi[(size_t)(bx + ty + j) * R + by + tx] = __float2half_rn(t[tx][ty + j]);
}

__global__ void __launch_bounds__(256)
wt_transpose_kernel(const float* __restrict__ Wq, const float* __restrict__ Wk,
                    const float* __restrict__ Wv, fp16* __restrict__ hi)
{
    const int z = blockIdx.z;
    const float* in = (z == 0) ? Wq : (z == 1) ? Wk : Wv;
    transpose_hi_body(in, hi + (size_t)z * DDIM * DDIM, DDIM, DDIM);
}

// ---------------------------------------------------------------------------
// 32x32 tiled fp16 -> fp16 transpose (pad 34 -> conflict-free).
// ---------------------------------------------------------------------------
__global__ void __launch_bounds__(256)
transpose16_kernel(const fp16* __restrict__ in, fp16* __restrict__ outp,
                   int Ri, int Ci)
{
    __shared__ __half t[32][34];
    const int bx = blockIdx.x * 32, by = blockIdx.y * 32;
    const int tx = threadIdx.x, ty = threadIdx.y;
    #pragma unroll
    for (int j = 0; j < 32; j += 8)
        t[ty + j][tx] = in[(size_t)(by + ty + j) * Ci + bx + tx];
    __syncthreads();
    #pragma unroll
    for (int j = 0; j < 32; j += 8)
        outp[(size_t)(bx + ty + j) * Ri + by + tx] = t[tx][ty + j];
}

// ---------------------------------------------------------------------------
// Exact per-row top-k on fp16 scores: 2-pass radix select on 16-bit
// order-preserving keys, then masked softmax (f32) emitting fp16 attn.
// ---------------------------------------------------------------------------
__global__ void __launch_bounds__(512)
topk_softmax_kernel(const fp16* __restrict__ scoreh, fp16* __restrict__ atth)
{
    __shared__ uint32_t hist[256];
    __shared__ uint32_t sh_sel[2];
    __shared__ float red[16];

    const int tid = threadIdx.x;
    const uint4* rowv = reinterpret_cast<const uint4*>(scoreh + (size_t)blockIdx.x * N_TOK);
    const uint4 pk = rowv[tid];

    float orig[8];
    uint32_t su[8];
    {
        const uint32_t wds[4] = {pk.x, pk.y, pk.z, pk.w};
        #pragma unroll
        for (int j = 0; j < 4; ++j) {
            const uint32_t x = wds[j];
            const uint32_t xr = x ^ (0x80008000u | (((x >> 15) & 0x00010001u) * 0x7FFFu));
            su[2 * j + 0] = xr & 0xFFFFu;
            su[2 * j + 1] = xr >> 16;
            const float2 f2 = __half22float2(*reinterpret_cast<const __half2*>(&x));
            orig[2 * j + 0] = f2.x;
            orig[2 * j + 1] = f2.y;
        }
    }

    uint32_t prefix = 0, rank = KEEP;
    #pragma unroll
    for (int pass = 0; pass < 2; ++pass) {
        const int shift = 8 - pass * 8;
        if (tid < 256) hist[tid] = 0;
        __syncthreads();
        #pragma unroll
        for (int j = 0; j < 8; ++j) {
            const uint32_t u = su[j];
            const bool match = (pass == 0) || ((u >> 8) == (prefix >> 8));
            if (match) atomicAdd(&hist[(u >> shift) & 0xFFu], 1u);
        }
        __syncthreads();
        if (tid < 32) {
            uint32_t h[8], sum = 0;
            #pragma unroll
            for (int i = 0; i < 8; ++i) {
                h[i] = hist[255 - (tid * 8 + i)];
                sum += h[i];
            }
            uint32_t inc = sum;
            #pragma unroll
            for (int o = 1; o < 32; o <<= 1) {
                const uint32_t t = __shfl_up_sync(0xffffffffu, inc, o);
                if (tid >= o) inc += t;
            }
            const uint32_t exc = inc - sum;
            if (exc < rank && rank <= inc) {
                uint32_t cum = exc;
                #pragma unroll
                for (int i = 0; i < 8; ++i) {
                    cum += h[i];
                    if (cum >= rank) {
                        sh_sel[0] = prefix | ((uint32_t)(255 - (tid * 8 + i)) << shift);
                        sh_sel[1] = rank - (cum - h[i]);
                        break;
                    }
                }
            }
        }
        __syncthreads();
        prefix = sh_sel[0];
        rank   = sh_sel[1];
        __syncthreads();
    }
    const uint32_t thr_u = prefix;

    float m[8];
    float lmax = 0.0f;
    #pragma unroll
    for (int j = 0; j < 8; ++j) {
        m[j] = (su[j] > thr_u) ? orig[j] : 0.0f;
        lmax = fmaxf(lmax, m[j]);
    }
    #pragma unroll
    for (int o = 16; o; o >>= 1)
        lmax = fmaxf(lmax, __shfl_xor_sync(0xffffffffu, lmax, o));
    if ((tid & 31) == 0) red[tid >> 5] = lmax;
    __syncthreads();
    float gmax;
    {
        float v2 = red[tid & 15];
        #pragma unroll
        for (int o = 8; o; o >>= 1)
            v2 = fmaxf(v2, __shfl_xor_sync(0xffffffffu, v2, o));
        gmax = v2;
    }
    __syncthreads();

    float e[8];
    float lsum = 0.0f;
    #pragma unroll
    for (int j = 0; j < 8; ++j) {
        e[j] = expf(m[j] - gmax);
        lsum += e[j];
    }
    #pragma unroll
    for (int o = 16; o; o >>= 1)
        lsum += __shfl_xor_sync(0xffffffffu, lsum, o);
    if ((tid & 31) == 0) red[tid >> 5] = lsum;
    __syncthreads();
    float gsum;
    {
        float v2 = red[tid & 15];
        #pragma unroll
        for (int o = 8; o; o >>= 1)
            v2 += __shfl_xor_sync(0xffffffffu, v2, o);
        gsum = v2;
    }

    const float inv = 1.0f / gsum;
    uint4 outp;
    uint32_t* ow = reinterpret_cast<uint32_t*>(&outp);
    #pragma unroll
    for (int j = 0; j < 4; ++j) {
        __half2 h2;
        h2.x = __float2half_rn(e[2 * j + 0] * inv);
        h2.y = __float2half_rn(e[2 * j + 1] * inv);
        ow[j] = *reinterpret_cast<uint32_t*>(&h2);
    }
    reinterpret_cast<uint4*>(atth + (size_t)blockIdx.x * N_TOK)[tid] = outp;
}

// ---------------------------------------------------------------------------
extern "C" void kernel_launch(void* const* d_in, const int* in_sizes, int n_in,
                              void* d_out, int out_size)
{
    const float* x  = (const float*)d_in[0];
    const float* Wq = (const float*)d_in[1];
    const float* bq = (const float*)d_in[2];
    const float* Wk = (const float*)d_in[3];
    const float* bk = (const float*)d_in[4];
    const float* Wv = (const float*)d_in[5];
    const float* bv = (const float*)d_in[6];
    float* out = (float*)d_out;

    fp16 *xh, *WTh, *qh, *kh, *vh, *kTh, *vTh, *scoreh, *atth;
    cudaGetSymbolAddress((void**)&xh,     g_xh);
    cudaGetSymbolAddress((void**)&WTh,    g_WTh);
    cudaGetSymbolAddress((void**)&qh,     g_qh);
    cudaGetSymbolAddress((void**)&kh,     g_kh);
    cudaGetSymbolAddress((void**)&vh,     g_vh);
    cudaGetSymbolAddress((void**)&kTh,    g_kTh);
    cudaGetSymbolAddress((void**)&vTh,    g_vTh);
    cudaGetSymbolAddress((void**)&scoreh, g_scoreh);
    cudaGetSymbolAddress((void**)&atth,   g_atth);

    cudaFuncSetAttribute(qkv_kernel,
                         cudaFuncAttributeMaxDynamicSharedMemorySize, GEMM_SMEM_BYTES);
    cudaFuncSetAttribute(mma_hf_kernel<false, true>,
                         cudaFuncAttributeMaxDynamicSharedMemorySize, GEMM_SMEM_BYTES);
    cudaFuncSetAttribute(ctx_kernel,
                         cudaFuncAttributeMaxDynamicSharedMemorySize, CTX_SMEM_BYTES);

    const float inv_sqrt_d = 1.0f / sqrtf((float)DDIM);
    const dim3 tb(32, 8);

    // x -> fp16; weights transposed -> fp16
    cvt_kernel<<<(N_TOK * DDIM) / 256, 256>>>(x, xh);
    wt_transpose_kernel<<<dim3(DDIM / 32, DDIM / 32, 3), tb>>>(Wq, Wk, Wv, WTh);

    // QKV merged: grid (4, 32, 3). q, k, v all fp16.
    qkv_kernel<<<dim3(DDIM / 128, N_TOK / 128, 3), 512, GEMM_SMEM_BYTES>>>(
        xh, WTh, bq, bk, bv, qh, kh, vh);

    // kT: k viewed as [512][4096] -> [4096][512]; vT: v [4096][512] -> [512][4096]
    transpose16_kernel<<<dim3(N_TOK / 32, DDIM / 32), tb>>>(kh, kTh, DDIM, N_TOK);
    transpose16_kernel<<<dim3(DDIM / 32, N_TOK / 32), tb>>>(vh, vTh, N_TOK, DDIM);

    // Score: M=N=4096, K=512 -> fp16 (scaled)
    mma_hf_kernel<false, true><<<dim3(N_TOK / 128, N_TOK / 128), 512, GEMM_SMEM_BYTES>>>(
        qh, DDIM, kTh, DDIM, nullptr, scoreh, N_TOK, DDIM, nullptr, inv_sqrt_d);

    // Exact top-k (2-pass, fp16 keys) + masked softmax -> fp16 attn
    topk_softmax_kernel<<<N_TOK, 512>>>(scoreh, atth);

    // Context: 128x64 tiles, K=4096 unsplit, direct f32 output
    ctx_kernel<<<dim3(DDIM / 64, N_TOK / 128), 512, CTX_SMEM_BYTES>>>(
        atth, vTh, out);
}

// round 16
// speedup vs baseline: 1.1630x; 1.1630x over previous
#include <cuda_runtime.h>
#include <cuda_fp16.h>
#include <cstdint>
#include <math.h>

#define N_TOK 4096
#define DDIM  512
#define KEEP  2048

// ---------------- device scratch (uint4 for 16B alignment) ----------------
__device__ uint4 g_xh  [N_TOK * DDIM / 8];
__device__ uint4 g_WTh [3 * DDIM * DDIM / 8];
__device__ uint4 g_qh  [N_TOK * DDIM / 8];
__device__ uint4 g_kh  [N_TOK * DDIM / 8];
__device__ uint4 g_vh  [N_TOK * DDIM / 8];
__device__ uint4 g_kTh [N_TOK * DDIM / 8];
__device__ uint4 g_vTh [N_TOK * DDIM / 8];
__device__ uint4 g_scoreh[(size_t)N_TOK * N_TOK / 8];
__device__ uint4 g_atth  [(size_t)N_TOK * N_TOK / 8];
__device__ uint4 g_parth [8 * (size_t)N_TOK * DDIM / 8];

typedef __half fp16;

// ---------------- helpers ----------------
__device__ __forceinline__ uint32_t smem_u32(const void* p) {
    uint32_t a;
    asm("{ .reg .u64 t; cvta.to.shared.u64 t, %1; cvt.u32.u64 %0, t; }"
        : "=r"(a) : "l"(p));
    return a;
}

#define CP16(dst, src) \
    asm volatile("cp.async.cg.shared.global [%0], [%1], 16;" :: "r"(dst), "l"(src) : "memory")
#define CP_COMMIT() asm volatile("cp.async.commit_group;" ::: "memory")
#define CP_WAIT1()  asm volatile("cp.async.wait_group 1;" ::: "memory")
#define CP_WAIT0()  asm volatile("cp.async.wait_group 0;" ::: "memory")

#define LDSM4(r, a)                                                             \
    asm volatile("ldmatrix.sync.aligned.m8n8.x4.shared.b16 {%0,%1,%2,%3}, [%4];" \
        : "=r"((r)[0]), "=r"((r)[1]), "=r"((r)[2]), "=r"((r)[3]) : "r"(a))

// m16n8k16 fp16 MMA, D += A*B (row.col), f32 accumulate
#define MMA16(cc, a, b)                                                         \
    asm volatile("mma.sync.aligned.m16n8k16.row.col.f32.f16.f16.f32 "           \
        "{%0,%1,%2,%3}, {%4,%5,%6,%7}, {%8,%9}, {%0,%1,%2,%3};"                 \
        : "+f"((cc)[0]), "+f"((cc)[1]), "+f"((cc)[2]), "+f"((cc)[3])            \
        : "r"((a)[0]), "r"((a)[1]), "r"((a)[2]), "r"((a)[3]),                   \
          "r"((b)[0]), "r"((b)[1]))

// ---------------------------------------------------------------------------
// Plain fp16 GEMM body 128x128 (f32 accum): C = scale*(A @ B^T) (+bias)
// BK=64, 512 threads, 16 warps 4x4, warp tile 32x32.
// Smem: 2 stages x 2 tiles x 128 rows x 144B = 73728 B -> 2 CTAs/SM.
// ---------------------------------------------------------------------------
#define TILE_B    18432
#define STAGE_ALL (2 * TILE_B)
#define GEMM_SMEM_BYTES (2 * STAGE_ALL)    // 73728

template<bool BIAS, bool HALF_OUT>
__device__ __forceinline__ void gemm_body(
    const fp16* __restrict__ A, int lda,
    const fp16* __restrict__ B, int ldb,
    float* __restrict__ C, fp16* __restrict__ Ch, int ldc,
    int K, const float* __restrict__ bias, float scale,
    int bx, int by, char* sm)
{
    const uint32_t smb = smem_u32(sm);

    const int tid  = threadIdx.x;
    const int w    = tid >> 5;
    const int lane = tid & 31;
    const int wm   = w & 3;
    const int wn   = w >> 2;
    const int g    = lane >> 2;
    const int tig  = lane & 3;

    const int lrow = tid >> 2;
    const int lch  = tid & 3;
    const fp16* pA = A + (size_t)(by * 128 + lrow) * lda + lch * 16;
    const fp16* pB = B + (size_t)(bx * 128 + lrow) * ldb + lch * 16;
    const uint32_t so = (uint32_t)lrow * 144 + lch * 32;

    const int l7 = lane & 7;
    const uint32_t aoff0 = (uint32_t)(wm * 32 + ((lane >> 3) & 1) * 8 + l7) * 144
                         + (uint32_t)(lane >> 4) * 16;
    const uint32_t aoff1 = aoff0 + 16u * 144u;
    const uint32_t boff0 = TILE_B
                         + (uint32_t)(wn * 32 + (lane >> 4) * 8 + l7) * 144
                         + (uint32_t)((lane >> 3) & 1) * 16;
    const uint32_t boff1 = boff0 + 16u * 144u;

    float c[2][4][4] = {};
    const int nT = K >> 6;

    {
        const uint32_t st = smb;
        CP16(st + so,               pA);
        CP16(st + so + 16,          pA + 8);
        CP16(st + TILE_B + so,      pB);
        CP16(st + TILE_B + so + 16, pB + 8);
        CP_COMMIT();
    }

    for (int kt = 0; kt < nT; ++kt) {
        if (kt + 1 < nT) {
            const uint32_t st = smb + ((kt + 1) & 1) * STAGE_ALL;
            const int ko = (kt + 1) * 64;
            CP16(st + so,               pA + ko);
            CP16(st + so + 16,          pA + ko + 8);
            CP16(st + TILE_B + so,      pB + ko);
            CP16(st + TILE_B + so + 16, pB + ko + 8);
            CP_COMMIT();
            CP_WAIT1();
        } else {
            CP_WAIT0();
        }
        __syncthreads();

        const uint32_t stb = smb + (kt & 1) * STAGE_ALL;

        #pragma unroll
        for (int ks = 0; ks < 4; ++ks) {
            const uint32_t koff = (uint32_t)ks * 32;

            uint32_t ah[2][4], bh[2][4];
            LDSM4(ah[0], stb + aoff0 + koff);
            LDSM4(ah[1], stb + aoff1 + koff);
            LDSM4(bh[0], stb + boff0 + koff);
            LDSM4(bh[1], stb + boff1 + koff);

            #pragma unroll
            for (int mi = 0; mi < 2; ++mi)
                #pragma unroll
                for (int ni = 0; ni < 4; ++ni)
                    MMA16(c[mi][ni], ah[mi], bh[ni >> 1] + (ni & 1) * 2);
        }
        __syncthreads();
    }

    #pragma unroll
    for (int mi = 0; mi < 2; ++mi) {
        const int r0 = by * 128 + wm * 32 + mi * 16 + g;
        #pragma unroll
        for (int ni = 0; ni < 4; ++ni) {
            const int col = bx * 128 + wn * 32 + ni * 8 + tig * 2;
            float vv[4];
            vv[0] = c[mi][ni][0] * scale; vv[1] = c[mi][ni][1] * scale;
            vv[2] = c[mi][ni][2] * scale; vv[3] = c[mi][ni][3] * scale;
            if (BIAS) {
                const float b0 = bias[col], b1 = bias[col + 1];
                vv[0] += b0; vv[1] += b1; vv[2] += b0; vv[3] += b1;
            }
            if (HALF_OUT) {
                __half2 t2;
                t2.x = __float2half_rn(vv[0]); t2.y = __float2half_rn(vv[1]);
                *reinterpret_cast<__half2*>(Ch + (size_t)r0 * ldc + col) = t2;
                t2.x = __float2half_rn(vv[2]); t2.y = __float2half_rn(vv[3]);
                *reinterpret_cast<__half2*>(Ch + (size_t)(r0 + 8) * ldc + col) = t2;
            } else {
                *reinterpret_cast<float2*>(C + (size_t)r0 * ldc + col)       = make_float2(vv[0], vv[1]);
                *reinterpret_cast<float2*>(C + (size_t)(r0 + 8) * ldc + col) = make_float2(vv[2], vv[3]);
            }
        }
    }
}

template<bool BIAS, bool HALF_OUT>
__global__ void __launch_bounds__(512, 2)
mma_hf_kernel(const fp16* __restrict__ A, int lda,
              const fp16* __restrict__ B, int ldb,
              float* __restrict__ C, fp16* __restrict__ Ch,
              int ldc, int K, const float* __restrict__ bias, float scale)
{
    extern __shared__ char sm[];
    gemm_body<BIAS, HALF_OUT>(A, lda, B, ldb, C, Ch, ldc,
                              K, bias, scale, blockIdx.x, blockIdx.y, sm);
}

// Merged QKV: grid (4, 32, 3); all outputs fp16 (bitwise identical to the
// old f32-store + transpose-time rounding).
__global__ void __launch_bounds__(512, 2)
qkv_kernel(const fp16* __restrict__ xh, const fp16* __restrict__ WTh,
           const float* __restrict__ bq, const float* __restrict__ bk,
           const float* __restrict__ bv,
           fp16* __restrict__ qh, fp16* __restrict__ kh, fp16* __restrict__ vh)
{
    extern __shared__ char sm[];
    const int z = blockIdx.z;
    const fp16* Wh = WTh + (size_t)z * DDIM * DDIM;
    fp16* outp = (z == 0) ? qh : (z == 1) ? kh : vh;
    const float* bias = (z == 0) ? bq : (z == 1) ? bk : bv;
    gemm_body<true, true>(xh, DDIM, Wh, DDIM, nullptr, outp,
                          DDIM, DDIM, bias, 1.0f, blockIdx.x, blockIdx.y, sm);
}

// Merged context split-K=8 (R13 config): grid (4, 32, 8); partials in fp16.
__global__ void __launch_bounds__(512, 2)
ctx_kernel(const fp16* __restrict__ atth, const fp16* __restrict__ vTh,
           fp16* __restrict__ parth)
{
    extern __shared__ char sm[];
    const int z = blockIdx.z;
    gemm_body<false, true>(atth + z * (N_TOK / 8), N_TOK,
                           vTh + z * (N_TOK / 8), N_TOK,
                           nullptr, parth + (size_t)z * N_TOK * DDIM, DDIM,
                           N_TOK / 8, nullptr, 1.0f, blockIdx.x, blockIdx.y, sm);
}

// ---------------------------------------------------------------------------
// prep: merged x->fp16 convert (blocks 0..1023, 8 floats/thread) and
// weight transpose f32->fp16 (blocks 1024..1791: 256 tiles per matrix x 3).
// ---------------------------------------------------------------------------
__global__ void __launch_bounds__(256)
prep_kernel(const float* __restrict__ x,
            const float* __restrict__ Wq, const float* __restrict__ Wk,
            const float* __restrict__ Wv,
            fp16* __restrict__ xh, fp16* __restrict__ WTh)
{
    __shared__ float t[32][33];
    const int bid = blockIdx.x;
    if (bid < 1024) {
        const int i = (bid * 256 + threadIdx.x) * 8;
        const float4 a = *reinterpret_cast<const float4*>(x + i);
        const float4 b = *reinterpret_cast<const float4*>(x + i + 4);
        uint4 o;
        __half2 h;
        h = __floats2half2_rn(a.x, a.y); o.x = *reinterpret_cast<uint32_t*>(&h);
        h = __floats2half2_rn(a.z, a.w); o.y = *reinterpret_cast<uint32_t*>(&h);
        h = __floats2half2_rn(b.x, b.y); o.z = *reinterpret_cast<uint32_t*>(&h);
        h = __floats2half2_rn(b.z, b.w); o.w = *reinterpret_cast<uint32_t*>(&h);
        *reinterpret_cast<uint4*>(xh + i) = o;
    } else {
        const int wid = bid - 1024;
        const int z = wid >> 8;          // 0..2
        const int tI = wid & 255;        // tile id within matrix
        const float* in = (z == 0) ? Wq : (z == 1) ? Wk : Wv;
        fp16* hi = WTh + (size_t)z * DDIM * DDIM;
        const int bx = (tI & 15) * 32, by = (tI >> 4) * 32;
        const int tx = threadIdx.x & 31, ty = threadIdx.x >> 5;
        #pragma unroll
        for (int j = 0; j < 32; j += 8)
            t[ty + j][tx] = in[(size_t)(by + ty + j) * DDIM + bx + tx];
        __syncthreads();
        #pragma unroll
        for (int j = 0; j < 32; j += 8)
            hi[(size_t)(bx + ty + j) * DDIM + by + tx] = __float2half_rn(t[tx][ty + j]);
    }
}

// ---------------------------------------------------------------------------
// Merged kT/vT fp16 transposes (pad-34 smem: conflict-free), 1-D grid decode.
// blocks 0..2047: kT (k viewed [512][4096] -> [4096][512])
// blocks 2048..4095: vT (v [4096][512] -> [512][4096])
// ---------------------------------------------------------------------------
__global__ void __launch_bounds__(256)
kv_transpose_kernel(const fp16* __restrict__ kh, const fp16* __restrict__ vh,
                    fp16* __restrict__ kTh, fp16* __restrict__ vTh)
{
    __shared__ __half t[32][34];
    const int bid = blockIdx.x;
    const fp16* in;
    fp16* outp;
    int Ri, Ci, bxi, byi;
    if (bid < 2048) {
        in = kh;  outp = kTh; Ri = DDIM;  Ci = N_TOK;
        bxi = bid & 127; byi = bid >> 7;
    } else {
        const int id = bid - 2048;
        in = vh;  outp = vTh; Ri = N_TOK; Ci = DDIM;
        bxi = id & 15;  byi = id >> 4;
    }
    const int bx = bxi * 32, by = byi * 32;
    const int tx = threadIdx.x & 31, ty = threadIdx.x >> 5;
    #pragma unroll
    for (int j = 0; j < 32; j += 8)
        t[ty + j][tx] = in[(size_t)(by + ty + j) * Ci + bx + tx];
    __syncthreads();
    #pragma unroll
    for (int j = 0; j < 32; j += 8)
        outp[(size_t)(bx + ty + j) * Ri + by + tx] = t[tx][ty + j];
}

// ---------------------------------------------------------------------------
// Exact per-row top-k on fp16 scores: 2-pass radix select on 16-bit
// order-preserving keys, then masked softmax (f32) emitting fp16 attn.
// ---------------------------------------------------------------------------
__global__ void __launch_bounds__(512)
topk_softmax_kernel(const fp16* __restrict__ scoreh, fp16* __restrict__ atth)
{
    __shared__ uint32_t hist[256];
    __shared__ uint32_t sh_sel[2];
    __shared__ float red[16];

    const int tid = threadIdx.x;
    const uint4* rowv = reinterpret_cast<const uint4*>(scoreh + (size_t)blockIdx.x * N_TOK);
    const uint4 pk = rowv[tid];

    float orig[8];
    uint32_t su[8];
    {
        const uint32_t wds[4] = {pk.x, pk.y, pk.z, pk.w};
        #pragma unroll
        for (int j = 0; j < 4; ++j) {
            const uint32_t xv = wds[j];
            const uint32_t xr = xv ^ (0x80008000u | (((xv >> 15) & 0x00010001u) * 0x7FFFu));
            su[2 * j + 0] = xr & 0xFFFFu;
            su[2 * j + 1] = xr >> 16;
            const float2 f2 = __half22float2(*reinterpret_cast<const __half2*>(&xv));
            orig[2 * j + 0] = f2.x;
            orig[2 * j + 1] = f2.y;
        }
    }

    uint32_t prefix = 0, rank = KEEP;
    #pragma unroll
    for (int pass = 0; pass < 2; ++pass) {
        const int shift = 8 - pass * 8;
        if (tid < 256) hist[tid] = 0;
        __syncthreads();
        #pragma unroll
        for (int j = 0; j < 8; ++j) {
            const uint32_t u = su[j];
            const bool match = (pass == 0) || ((u >> 8) == (prefix >> 8));
            if (match) atomicAdd(&hist[(u >> shift) & 0xFFu], 1u);
        }
        __syncthreads();
        if (tid < 32) {
            uint32_t h[8], sum = 0;
            #pragma unroll
            for (int i = 0; i < 8; ++i) {
                h[i] = hist[255 - (tid * 8 + i)];
                sum += h[i];
            }
            uint32_t inc = sum;
            #pragma unroll
            for (int o = 1; o < 32; o <<= 1) {
                const uint32_t t = __shfl_up_sync(0xffffffffu, inc, o);
                if (tid >= o) inc += t;
            }
            const uint32_t exc = inc - sum;
            if (exc < rank && rank <= inc) {
                uint32_t cum = exc;
                #pragma unroll
                for (int i = 0; i < 8; ++i) {
                    cum += h[i];
                    if (cum >= rank) {
                        sh_sel[0] = prefix | ((uint32_t)(255 - (tid * 8 + i)) << shift);
                        sh_sel[1] = rank - (cum - h[i]);
                        break;
                    }
                }
            }
        }
        __syncthreads();
        prefix = sh_sel[0];
        rank   = sh_sel[1];
        __syncthreads();
    }
    const uint32_t thr_u = prefix;

    float m[8];
    float lmax = 0.0f;
    #pragma unroll
    for (int j = 0; j < 8; ++j) {
        m[j] = (su[j] > thr_u) ? orig[j] : 0.0f;
        lmax = fmaxf(lmax, m[j]);
    }
    #pragma unroll
    for (int o = 16; o; o >>= 1)
        lmax = fmaxf(lmax, __shfl_xor_sync(0xffffffffu, lmax, o));
    if ((tid & 31) == 0) red[tid >> 5] = lmax;
    __syncthreads();
    float gmax;
    {
        float v2 = red[tid & 15];
        #pragma unroll
        for (int o = 8; o; o >>= 1)
            v2 = fmaxf(v2, __shfl_xor_sync(0xffffffffu, v2, o));
        gmax = v2;
    }
    __syncthreads();

    float e[8];
    float lsum = 0.0f;
    #pragma unroll
    for (int j = 0; j < 8; ++j) {
        e[j] = expf(m[j] - gmax);
        lsum += e[j];
    }
    #pragma unroll
    for (int o = 16; o; o >>= 1)
        lsum += __shfl_xor_sync(0xffffffffu, lsum, o);
    if ((tid & 31) == 0) red[tid >> 5] = lsum;
    __syncthreads();
    float gsum;
    {
        float v2 = red[tid & 15];
        #pragma unroll
        for (int o = 8; o; o >>= 1)
            v2 += __shfl_xor_sync(0xffffffffu, v2, o);
        gsum = v2;
    }

    const float inv = 1.0f / gsum;
    uint4 outp;
    uint32_t* ow = reinterpret_cast<uint32_t*>(&outp);
    #pragma unroll
    for (int j = 0; j < 4; ++j) {
        __half2 h2;
        h2.x = __float2half_rn(e[2 * j + 0] * inv);
        h2.y = __float2half_rn(e[2 * j + 1] * inv);
        ow[j] = *reinterpret_cast<uint32_t*>(&h2);
    }
    reinterpret_cast<uint4*>(atth + (size_t)blockIdx.x * N_TOK)[tid] = outp;
}

// ---------------------------------------------------------------------------
// Deterministic 8-way split-K reduce: fp16 partials -> f32 out (fixed order)
// ---------------------------------------------------------------------------
__global__ void __launch_bounds__(256)
reduce8_kernel(const uint4* __restrict__ parth, float4* __restrict__ out)
{
    const int i = blockIdx.x * blockDim.x + threadIdx.x;   // 8 halves per thread
    const size_t stride = (size_t)N_TOK * DDIM / 8;
    float acc[8] = {};
    #pragma unroll
    for (int z = 0; z < 8; ++z) {
        const uint4 p = parth[(size_t)z * stride + i];
        const uint32_t wds[4] = {p.x, p.y, p.z, p.w};
        #pragma unroll
        for (int j = 0; j < 4; ++j) {
            const float2 f = __half22float2(*reinterpret_cast<const __half2*>(&wds[j]));
            acc[2 * j]     += f.x;
            acc[2 * j + 1] += f.y;
        }
    }
    out[2 * i]     = make_float4(acc[0], acc[1], acc[2], acc[3]);
    out[2 * i + 1] = make_float4(acc[4], acc[5], acc[6], acc[7]);
}

// ---------------------------------------------------------------------------
extern "C" void kernel_launch(void* const* d_in, const int* in_sizes, int n_in,
                              void* d_out, int out_size)
{
    const float* x  = (const float*)d_in[0];
    const float* Wq = (const float*)d_in[1];
    const float* bq = (const float*)d_in[2];
    const float* Wk = (const float*)d_in[3];
    const float* bk = (const float*)d_in[4];
    const float* Wv = (const float*)d_in[5];
    const float* bv = (const float*)d_in[6];
    float* out = (float*)d_out;

    fp16 *xh, *WTh, *qh, *kh, *vh, *kTh, *vTh, *scoreh, *atth, *parth;
    cudaGetSymbolAddress((void**)&xh,     g_xh);
    cudaGetSymbolAddress((void**)&WTh,    g_WTh);
    cudaGetSymbolAddress((void**)&qh,     g_qh);
    cudaGetSymbolAddress((void**)&kh,     g_kh);
    cudaGetSymbolAddress((void**)&vh,     g_vh);
    cudaGetSymbolAddress((void**)&kTh,    g_kTh);
    cudaGetSymbolAddress((void**)&vTh,    g_vTh);
    cudaGetSymbolAddress((void**)&scoreh, g_scoreh);
    cudaGetSymbolAddress((void**)&atth,   g_atth);
    cudaGetSymbolAddress((void**)&parth,  g_parth);

    cudaFuncSetAttribute(qkv_kernel,
                         cudaFuncAttributeMaxDynamicSharedMemorySize, GEMM_SMEM_BYTES);
    cudaFuncSetAttribute(mma_hf_kernel<false, true>,
                         cudaFuncAttributeMaxDynamicSharedMemorySize, GEMM_SMEM_BYTES);
    cudaFuncSetAttribute(ctx_kernel,
                         cudaFuncAttributeMaxDynamicSharedMemorySize, GEMM_SMEM_BYTES);

    const float inv_sqrt_d = 1.0f / sqrtf((float)DDIM);

    // Merged prep: x -> fp16 (1024 blocks) + 3 weight transposes (768 blocks)
    prep_kernel<<<1792, 256>>>(x, Wq, Wk, Wv, xh, WTh);

    // QKV merged: grid (4, 32, 3). q, k, v all fp16.
    qkv_kernel<<<dim3(DDIM / 128, N_TOK / 128, 3), 512, GEMM_SMEM_BYTES>>>(
        xh, WTh, bq, bk, bv, qh, kh, vh);

    // Merged kT + vT transposes (4096 blocks)
    kv_transpose_kernel<<<4096, 256>>>(kh, vh, kTh, vTh);

    // Score: M=N=4096, K=512 -> fp16 (scaled)
    mma_hf_kernel<false, true><<<dim3(N_TOK / 128, N_TOK / 128), 512, GEMM_SMEM_BYTES>>>(
        qh, DDIM, kTh, DDIM, nullptr, scoreh, N_TOK, DDIM, nullptr, inv_sqrt_d);

    // Exact top-k (2-pass, fp16 keys) + masked softmax -> fp16 attn
    topk_softmax_kernel<<<N_TOK, 512>>>(scoreh, atth);

    // Context: split-K=8, fp16 partials, deterministic f32 reduce
    ctx_kernel<<<dim3(DDIM / 128, N_TOK / 128, 8), 512, GEMM_SMEM_BYTES>>>(
        atth, vTh, parth);
    reduce8_kernel<<<(N_TOK * DDIM / 8) / 256, 256>>>(
        (const uint4*)parth, (float4*)out);
}